// round 14
// baseline (speedup 1.0000x reference)
#include <cuda_runtime.h>
#include <cuda_fp16.h>
#include <cstdint>
#include <math.h>

// ---------------- problem constants ----------------
#define EDIM 1140
#define KP   1144            // EDIM padded to mult of 8 (fp16 16B chunks)
#define HH   1120
#define NH   32
#define HS   35
#define NL   36
#define VOC  45000
#define TT   128
#define BB   8
#define MM   1024
#define FF   4560
#define QKVN 3360
#define ATT_SCALE 0.16903085094570331f

// ---------------- converted-weight layout (fp16, transposed [N][K]) ----------------
#define SZQ  (1120*KP)
#define OFF_QKV ((size_t)0)
#define SZWO (1140*1120)
#define OFF_WO  ((size_t)NL*3*SZQ)
#define SZW1 (4560*KP)
#define OFF_W1  (OFF_WO + (size_t)NL*SZWO)
#define SZW2 (1140*4560)
#define OFF_W2  (OFF_W1 + (size_t)NL*SZW1)
#define OFF_WH  (OFF_W2 + (size_t)NL*SZW2)
#define WTOT    (OFF_WH + (size_t)VOC*KP)

// ---------------- scratch (device globals) ----------------
__device__ float  g_x[MM * EDIM];
__device__ float  g_qkv[MM * QKVN];
__device__ float  g_part[4 * MM * EDIM];
__device__ __half g_y16[MM * KP];
__device__ __half g_att16[MM * HH];
__device__ __half g_h16[MM * FF];
__device__ __half g_w16[WTOT];
__device__ int    g_is64;

// ---------------- helpers ----------------
__device__ __forceinline__ uint32_t smem_u32(const void* p) {
    uint32_t a;
    asm("{ .reg .u64 t; cvta.to.shared.u64 t, %1; cvt.u32.u64 %0, t; }" : "=r"(a) : "l"(p));
    return a;
}
__device__ __forceinline__ void cpa16(uint32_t s, const void* g) {
    asm volatile("cp.async.cg.shared.global [%0], [%1], 16;" :: "r"(s), "l"(g) : "memory");
}
__device__ __forceinline__ void zfill16(uint32_t s) {
    asm volatile("st.shared.v4.b32 [%0], {%1,%1,%1,%1};" :: "r"(s), "r"(0) : "memory");
}
__device__ __forceinline__ void mma_f16(float* d, const uint32_t* a, const uint32_t* b) {
    asm volatile(
        "mma.sync.aligned.m16n8k16.row.col.f32.f16.f16.f32 "
        "{%0,%1,%2,%3}, {%4,%5,%6,%7}, {%8,%9}, {%0,%1,%2,%3};"
        : "+f"(d[0]), "+f"(d[1]), "+f"(d[2]), "+f"(d[3])
        : "r"(a[0]), "r"(a[1]), "r"(a[2]), "r"(a[3]), "r"(b[0]), "r"(b[1]));
}
__device__ __forceinline__ void ldsm4(uint32_t* r, uint32_t a) {
    asm volatile("ldmatrix.sync.aligned.m8n8.x4.shared.b16 {%0,%1,%2,%3}, [%4];"
        : "=r"(r[0]), "=r"(r[1]), "=r"(r[2]), "=r"(r[3]) : "r"(a));
}
__device__ __forceinline__ void ldsm2(uint32_t* r, uint32_t a) {
    asm volatile("ldmatrix.sync.aligned.m8n8.x2.shared.b16 {%0,%1}, [%2];"
        : "=r"(r[0]), "=r"(r[1]) : "r"(a));
}

// ---------------- index dtype detection ----------------
__global__ void detect_k(const int* __restrict__ raw) {
    __shared__ int any;
    if (threadIdx.x == 0) any = 0;
    __syncthreads();
    int local = 0;
    for (int i = threadIdx.x; i < 512; i += blockDim.x)
        if (raw[2 * i + 1] != 0) local = 1;
    if (local) atomicOr(&any, 1);
    __syncthreads();
    if (threadIdx.x == 0) g_is64 = any ? 0 : 1;
}

// ---------------- weight convert: f32 [K][N] -> fp16 [N][KPad] (RN), zero K-pad ----------
__global__ void convT_k(const float* __restrict__ in, __half* __restrict__ out,
                        int K, int N, int KPad, size_t inLs, size_t outLs) {
    in  += (size_t)blockIdx.z * inLs;
    out += (size_t)blockIdx.z * outLs;
    __shared__ float t[64][33];
    int bn = blockIdx.x * 32, bk = blockIdx.y * 64;
    int x = threadIdx.x, y = threadIdx.y;
#pragma unroll
    for (int i = 0; i < 64; i += 8) {
        int k = bk + y + i, n = bn + x;
        t[y + i][x] = (k < K && n < N) ? in[(size_t)k * N + n] : 0.f;
    }
    __syncthreads();
#pragma unroll
    for (int i = 0; i < 32; i += 8) {
        int n = bn + y + i;
        int k = bk + 2 * x;
        if (n < N && k < KPad) {
            __half2 h = __halves2half2(__float2half_rn(t[2 * x][y + i]),
                                       __float2half_rn(t[2 * x + 1][y + i]));
            *(__half2*)(out + (size_t)n * KPad + k) = h;
        }
    }
}

// fused QKV conversion: z = layer*3 + which, which in {0=q,1=k,2=v}
__global__ void convQKV_k(const float* __restrict__ wq,
                          const float* __restrict__ wk,
                          const float* __restrict__ wv,
                          __half* __restrict__ out) {
    int zz = blockIdx.z;
    int l = zz / 3, w = zz % 3;
    const float* in = ((w == 0) ? wq : (w == 1) ? wk : wv) + (size_t)l * EDIM * HH;
    __half* o = out + (size_t)l * 3 * SZQ + (size_t)w * SZQ;
    __shared__ float t[64][33];
    int bn = blockIdx.x * 32, bk = blockIdx.y * 64;
    int x = threadIdx.x, y = threadIdx.y;
#pragma unroll
    for (int i = 0; i < 64; i += 8) {
        int k = bk + y + i, n = bn + x;
        t[y + i][x] = (k < EDIM && n < HH) ? in[(size_t)k * HH + n] : 0.f;
    }
    __syncthreads();
#pragma unroll
    for (int i = 0; i < 32; i += 8) {
        int n = bn + y + i;
        int k = bk + 2 * x;
        if (n < HH && k < KP) {
            __half2 h = __halves2half2(__float2half_rn(t[2 * x][y + i]),
                                       __float2half_rn(t[2 * x + 1][y + i]));
            *(__half2*)(o + (size_t)n * KP + k) = h;
        }
    }
}

// ---------------- block row-LN from smem values -> y16 (fp16, zero-padded to KP) ----------------
__device__ __forceinline__ void row_ln_emit(const float* v, float s, float s2,
                                            const float* g, const float* b,
                                            __half* yrow) {
    __shared__ float sh0[8], sh1[8];
    for (int o = 16; o > 0; o >>= 1) {
        s  += __shfl_down_sync(0xffffffffu, s, o);
        s2 += __shfl_down_sync(0xffffffffu, s2, o);
    }
    int w = threadIdx.x >> 5, lane = threadIdx.x & 31;
    if (lane == 0) { sh0[w] = s; sh1[w] = s2; }
    __syncthreads();
    if (threadIdx.x == 0) {
        float ts = 0.f, ts2 = 0.f;
        for (int i = 0; i < 8; i++) { ts += sh0[i]; ts2 += sh1[i]; }
        float mu = ts / (float)EDIM;
        float var = ts2 / (float)EDIM - mu * mu;
        sh0[0] = mu;
        sh1[0] = rsqrtf(var + 1e-5f);
    }
    __syncthreads();
    float mu = sh0[0], rstd = sh1[0];
    for (int c = threadIdx.x; c < KP; c += blockDim.x) {
        float o = (c < EDIM) ? (v[c] - mu) * rstd * g[c] + b[c] : 0.f;
        yrow[c] = __float2half_rn(o);
    }
}

// ---------------- embedding + LN1(layer0) ----------------
__global__ void embed_ln_k(const int* __restrict__ raw,
                           const float* __restrict__ tok,
                           const float* __restrict__ pos,
                           const float* __restrict__ g,
                           const float* __restrict__ b,
                           float* __restrict__ x, __half* __restrict__ y16) {
    __shared__ float v[EDIM];
    int r = blockIdx.x, t = r % TT;
    int idx = g_is64 ? raw[2 * r] : raw[r];
    const float* te = tok + (size_t)idx * EDIM;
    const float* pe = pos + (size_t)t * EDIM;
    float s = 0.f, s2 = 0.f;
    for (int c = threadIdx.x; c < EDIM; c += blockDim.x) {
        float val = te[c] + pe[c];
        v[c] = val;
        x[(size_t)r * EDIM + c] = val;
        s += val; s2 = fmaf(val, val, s2);
    }
    __syncthreads();
    row_ln_emit(v, s, s2, g, b, y16 + (size_t)r * KP);
}

// ---------------- split-K reduce (bias pre-added in z=0 partial) + residual; LN -> y16 -----
__global__ void reduce4ln_k(const float* __restrict__ part,
                            float* __restrict__ x,
                            const float* __restrict__ g,
                            const float* __restrict__ b,
                            __half* __restrict__ y16) {
    __shared__ float v[EDIM];
    int r = blockIdx.x;
    const float4* p0 = (const float4*)(part + (size_t)r * EDIM);
    const float4* p1 = (const float4*)(part + (size_t)MM * EDIM + (size_t)r * EDIM);
    const float4* p2 = (const float4*)(part + (size_t)2 * MM * EDIM + (size_t)r * EDIM);
    const float4* p3 = (const float4*)(part + (size_t)3 * MM * EDIM + (size_t)r * EDIM);
    float4* xr = (float4*)(x + (size_t)r * EDIM);
    float s = 0.f, s2 = 0.f;
    for (int c = threadIdx.x; c < EDIM / 4; c += blockDim.x) {
        float4 a0 = p0[c], a1 = p1[c], a2 = p2[c], a3 = p3[c];
        float4 xv = xr[c];
        float4 val;
        val.x = ((a0.x + a1.x) + (a2.x + a3.x)) + xv.x;
        val.y = ((a0.y + a1.y) + (a2.y + a3.y)) + xv.y;
        val.z = ((a0.z + a1.z) + (a2.z + a3.z)) + xv.z;
        val.w = ((a0.w + a1.w) + (a2.w + a3.w)) + xv.w;
        xr[c] = val;
        *(float4*)(v + 4 * c) = val;
        s += val.x + val.y + val.z + val.w;
        s2 = fmaf(val.x, val.x, s2);
        s2 = fmaf(val.y, val.y, s2);
        s2 = fmaf(val.z, val.z, s2);
        s2 = fmaf(val.w, val.w, s2);
    }
    __syncthreads();
    row_ln_emit(v, s, s2, g, b, y16 + (size_t)r * KP);
}

// ---------------- fp16 tensor-core GEMM (BKK=64, 3-stage), templated on BN ----------------
// mode 0: plain f32  1: +bias f32  2: relu(+bias) -> fp16 C16
// mode 4: raw partial f32 (kchunk>0); z==0 chunk adds bias (pre-add for reduce)
#define BKK 64
#define ASTH 72                         // smem pitch in halfs (144 B, ldsm conflict-free)
#define NSTG 3

template<int BN>
__device__ __forceinline__ void load_slab_h(const __half* __restrict__ A,
                                            const __half* __restrict__ B,
                                            int Nc, int lda, int kend,
                                            int bm, int bn, int k0,
                                            uint32_t sA, uint32_t sB, int tid) {
#pragma unroll
    for (int i = 0; i < 4; i++) {                  // A: 128 rows x 64 k
        int c = tid + i * 256;
        int row = c >> 3;
        int kc = (c & 7) * 8;
        int gk = k0 + kc;
        uint32_t off = sA + (uint32_t)(row * ASTH + kc) * 2;
        if (gk < kend) cpa16(off, A + (size_t)(bm + row) * lda + gk);
        else           zfill16(off);
    }
#pragma unroll
    for (int i = 0; i < BN / 32; i++) {            // B: BN n-rows x 64 k
        int c = tid + i * 256;
        int row = c >> 3;
        int kc = (c & 7) * 8;
        int gk = k0 + kc;
        uint32_t off = sB + (uint32_t)(row * ASTH + kc) * 2;
        if (gk < kend && (bn + row) < Nc) cpa16(off, B + (size_t)(bn + row) * lda + gk);
        else                              zfill16(off);
    }
}

template<int BN>
__global__ void __launch_bounds__(256, 2)
hgemm_k(const __half* __restrict__ A,
        const __half* __restrict__ B0,
        const float* __restrict__ bias,
        float* __restrict__ C, __half* __restrict__ C16,
        int Nc, int K, int lda, int ldc, int mode, int kchunk) {
    constexpr int NT = BN / 32;                 // n-subtiles per warp
    constexpr int WNT = NT * 8;                 // warp n-tile
    constexpr int STG_H = (128 + BN) * ASTH;

    extern __shared__ __half smh[];

    int z = blockIdx.z;
    const __half* Bm = B0;
    int kb, ke;
    size_t rowoff;
    bool addb = (mode == 1 || mode == 2);
    if (kchunk > 0) {
        kb = z * kchunk;
        ke = min(K, kb + kchunk);
        rowoff = (size_t)z * MM;
        addb = (z == 0);                      // fold bias into first partial
    } else {
        kb = 0; ke = K;
        rowoff = 0;
    }

    int tid = threadIdx.x;
    int bn = blockIdx.x * BN, bm = blockIdx.y * 128;
    int warp = tid >> 5, lane = tid & 31;
    int wm = warp >> 2, wn = warp & 3;          // 2 x 4 warp grid
    int g = lane >> 2, tig = lane & 3;

    int lrow = lane & 15;
    int koff8 = (lane & 16) ? 8 : 0;
    int l8 = lane & 7;
    int koff8b = (lane & 8) ? 8 : 0;

    uint32_t sbase = smem_u32(smh);

    float acc[4][NT][4];
#pragma unroll
    for (int mt = 0; mt < 4; mt++)
#pragma unroll
        for (int nt = 0; nt < NT; nt++)
#pragma unroll
            for (int j = 0; j < 4; j++) acc[mt][nt][j] = 0.f;

    const int NS = (ke - kb + BKK - 1) / BKK;

    // prologue: stages 0,1 in flight
#pragma unroll
    for (int s = 0; s < 2; s++) {
        if (s < NS)
            load_slab_h<BN>(A, Bm, Nc, lda, ke, bm, bn, kb + s * BKK,
                            sbase + (uint32_t)(s * STG_H) * 2,
                            sbase + (uint32_t)(s * STG_H + 128 * ASTH) * 2, tid);
        asm volatile("cp.async.commit_group;" ::: "memory");
    }
    asm volatile("cp.async.wait_group 1;" ::: "memory");   // stage 0 ready
    __syncthreads();

    int cst = 0, lst = 2;

    for (int ksl = 0; ksl < NS; ksl++) {
        // loads FIRST: slab ksl+2 into stage lst (consumed at ksl-1, barrier-separated)
        if (ksl + 2 < NS)
            load_slab_h<BN>(A, Bm, Nc, lda, ke, bm, bn, kb + (ksl + 2) * BKK,
                            sbase + (uint32_t)(lst * STG_H) * 2,
                            sbase + (uint32_t)(lst * STG_H + 128 * ASTH) * 2, tid);
        asm volatile("cp.async.commit_group;" ::: "memory");

        uint32_t sA = sbase + (uint32_t)(cst * STG_H) * 2;
        uint32_t sB = sA + (uint32_t)(128 * ASTH) * 2;
        uint32_t aw = sA + (uint32_t)((wm * 64 + lrow) * ASTH + koff8) * 2;
        uint32_t bw = sB + (uint32_t)((wn * WNT + lrow) * ASTH + koff8) * 2;
        uint32_t bw2 = sB + (uint32_t)((wn * WNT + 16 + l8) * ASTH + koff8b) * 2;

        // compute this slab: 4 k-slices of 16
#pragma unroll
        for (int ks = 0; ks < 4; ks++) {
            uint32_t kb2 = (uint32_t)(ks * 16) * 2;
            uint32_t a[4][4];
#pragma unroll
            for (int mt = 0; mt < 4; mt++)
                ldsm4(a[mt], aw + (uint32_t)(mt * 16 * ASTH) * 2 + kb2);

            uint32_t bcol[NT][2];
            if (BN == 128) {
                uint32_t b0[4], b1[4];
                ldsm4(b0, bw + kb2);
                ldsm4(b1, bw + (uint32_t)(16 * ASTH) * 2 + kb2);
                bcol[0][0] = b0[0]; bcol[0][1] = b0[2];
                bcol[1][0] = b0[1]; bcol[1][1] = b0[3];
                bcol[2][0] = b1[0]; bcol[2][1] = b1[2];
                bcol[NT - 1][0] = b1[1]; bcol[NT - 1][1] = b1[3];
            } else {
                uint32_t b0[4], b1[2];
                ldsm4(b0, bw + kb2);
                ldsm2(b1, bw2 + kb2);
                bcol[0][0] = b0[0]; bcol[0][1] = b0[2];
                bcol[1][0] = b0[1]; bcol[1][1] = b0[3];
                bcol[NT - 1][0] = b1[0]; bcol[NT - 1][1] = b1[1];
            }
#pragma unroll
            for (int mt = 0; mt < 4; mt++)
#pragma unroll
                for (int nt = 0; nt < NT; nt++)
                    mma_f16(acc[mt][nt], a[mt], bcol[nt]);
        }

        asm volatile("cp.async.wait_group 1;" ::: "memory");  // stage ksl+1 ready
        __syncthreads();

        if (++cst == NSTG) cst = 0;
        if (++lst == NSTG) lst = 0;
    }

    // epilogue
    bool fullN = (bn + BN) <= Nc;
#pragma unroll
    for (int mt = 0; mt < 4; mt++) {
        size_t r0 = rowoff + bm + wm * 64 + mt * 16 + g;
        size_t r1 = r0 + 8;
#pragma unroll
        for (int nt = 0; nt < NT; nt++) {
            int col = bn + wn * WNT + nt * 8 + 2 * tig;
            float v0 = acc[mt][nt][0], v1 = acc[mt][nt][1];
            float v2 = acc[mt][nt][2], v3 = acc[mt][nt][3];
            if (fullN) {
                if (addb) {
                    float2 bb = *(const float2*)(bias + col);
                    v0 += bb.x; v1 += bb.y; v2 += bb.x; v3 += bb.y;
                }
                if (mode == 2) {
                    __half2 h0 = __halves2half2(__float2half_rn(fmaxf(v0, 0.f)),
                                                __float2half_rn(fmaxf(v1, 0.f)));
                    __half2 h1 = __halves2half2(__float2half_rn(fmaxf(v2, 0.f)),
                                                __float2half_rn(fmaxf(v3, 0.f)));
                    *(__half2*)(C16 + r0 * ldc + col) = h0;
                    *(__half2*)(C16 + r1 * ldc + col) = h1;
                } else {
                    *(float2*)(C + r0 * ldc + col) = make_float2(v0, v1);
                    *(float2*)(C + r1 * ldc + col) = make_float2(v2, v3);
                }
            } else {
                float vv[4] = {v0, v1, v2, v3};
                size_t rr[4] = {r0, r0, r1, r1};
                int cc[4] = {col, col + 1, col, col + 1};
#pragma unroll
                for (int j = 0; j < 4; j++) {
                    if (cc[j] >= Nc) continue;
                    float v = vv[j];
                    if (addb) v += bias[cc[j]];
                    if (mode == 2)
                        C16[rr[j] * ldc + cc[j]] = __float2half_rn(fmaxf(v, 0.f));
                    else
                        C[rr[j] * ldc + cc[j]] = v;
                }
            }
        }
    }
}

#define DS96  (NSTG * (128 + 96)  * ASTH * 2)   // 96768 B
#define DS128 (NSTG * (128 + 128) * ASTH * 2)   // 110592 B

// ---------------- attention: 8-way split over s per query, shfl merge ----------------
__global__ void __launch_bounds__(128)
attn_k(const float* __restrict__ qkv, __half* __restrict__ att) {
    __shared__ float ks[TT][HS + 1];
    __shared__ float vs[TT][HS + 1];

    int bh = blockIdx.x;
    int b = bh / NH, h = bh % NH;
    int qy = blockIdx.y;
    int tid = threadIdx.x;
    int t = qy * 16 + (tid >> 3);
    int sub = tid & 7;
    const size_t rbase = (size_t)b * TT * QKVN;
    const int hoff = h * HS;
    const int rows = qy * 16 + 16;      // causal trim

    for (int idx = tid; idx < rows * HS; idx += 128) {
        int s = idx / HS, d = idx % HS;
        ks[s][d] = qkv[rbase + (size_t)s * QKVN + HH + hoff + d];
        vs[s][d] = qkv[rbase + (size_t)s * QKVN + 2 * HH + hoff + d];
    }
    __syncthreads();

    float qreg[HS];
#pragma unroll
    for (int d = 0; d < HS; d++)
        qreg[d] = qkv[rbase + (size_t)t * QKVN + hoff + d];

    float m = -1e30f, l = 0.f;
    float out[HS];
#pragma unroll
    for (int d = 0; d < HS; d++) out[d] = 0.f;

    for (int s = sub; s <= t; s += 8) {
        float dot = 0.f;
#pragma unroll
        for (int d = 0; d < HS; d++)
            dot = fmaf(qreg[d], ks[s][d], dot);
        float sc = dot * ATT_SCALE;
        float mn = fmaxf(m, sc);
        float corr = expf(m - mn);
        float p = expf(sc - mn);
        l = l * corr + p;
#pragma unroll
        for (int d = 0; d < HS; d++)
            out[d] = out[d] * corr + p * vs[s][d];
        m = mn;
    }

    float M = m;
#pragma unroll
    for (int o = 1; o < 8; o <<= 1)
        M = fmaxf(M, __shfl_xor_sync(0xffffffffu, M, o));
    float e = expf(m - M);
    float ls = l * e;
#pragma unroll
    for (int o = 1; o < 8; o <<= 1)
        ls += __shfl_xor_sync(0xffffffffu, ls, o);
    float inv = 1.f / ls;

    size_t obase = (size_t)(b * TT + t) * HH + hoff;
#pragma unroll
    for (int d = 0; d < HS; d++) {
        float ov = out[d] * e;
#pragma unroll
        for (int o2 = 1; o2 < 8; o2 <<= 1)
            ov += __shfl_xor_sync(0xffffffffu, ov, o2);
        if (sub == 0) att[obase + d] = __float2half_rn(ov * inv);
    }
}

// ---------------- launcher ----------------
extern "C" void kernel_launch(void* const* d_in, const int* in_sizes, int n_in,
                              void* d_out, int out_size) {
    (void)in_sizes; (void)n_in; (void)out_size;
    const int*   index = (const int*)  d_in[0];
    const float* tok   = (const float*)d_in[1];
    const float* pos   = (const float*)d_in[2];
    const float* wq    = (const float*)d_in[3];
    const float* wk    = (const float*)d_in[4];
    const float* wv    = (const float*)d_in[5];
    const float* wo    = (const float*)d_in[6];
    const float* bo    = (const float*)d_in[7];
    const float* ln1g  = (const float*)d_in[8];
    const float* ln1b  = (const float*)d_in[9];
    const float* ln2g  = (const float*)d_in[10];
    const float* ln2b  = (const float*)d_in[11];
    const float* w1    = (const float*)d_in[12];
    const float* b1    = (const float*)d_in[13];
    const float* w2    = (const float*)d_in[14];
    const float* b2    = (const float*)d_in[15];
    const float* lnfg  = (const float*)d_in[16];
    const float* lnfb  = (const float*)d_in[17];
    const float* wh    = (const float*)d_in[18];
    const float* bh    = (const float*)d_in[19];
    float* out = (float*)d_out;

    float *x, *qkv, *part;
    __half *y16, *att16, *h16, *w16;
    cudaGetSymbolAddress((void**)&x,     g_x);
    cudaGetSymbolAddress((void**)&qkv,   g_qkv);
    cudaGetSymbolAddress((void**)&part,  g_part);
    cudaGetSymbolAddress((void**)&y16,   g_y16);
    cudaGetSymbolAddress((void**)&att16, g_att16);
    cudaGetSymbolAddress((void**)&h16,   g_h16);
    cudaGetSymbolAddress((void**)&w16,   g_w16);

    cudaFuncSetAttribute((void*)hgemm_k<96>,
                         cudaFuncAttributeMaxDynamicSharedMemorySize, DS96);
    cudaFuncSetAttribute((void*)hgemm_k<128>,
                         cudaFuncAttributeMaxDynamicSharedMemorySize, DS128);

    dim3 tb(32, 8);

    detect_k<<<1, 256>>>(index);

    // ---- convert all weights: f32 [K][N] -> fp16 [N][KPad], once per launch ----
    convQKV_k<<<dim3(35, 18, 3 * NL), tb>>>(wq, wk, wv, w16 + OFF_QKV);
    convT_k<<<dim3(36, 18, NL), tb>>>(wo, w16 + OFF_WO,   HH, EDIM, HH,
                                      (size_t)HH * EDIM, (size_t)SZWO);
    convT_k<<<dim3(143, 18, NL), tb>>>(w1, w16 + OFF_W1,  EDIM, FF, KP,
                                      (size_t)EDIM * FF, (size_t)SZW1);
    convT_k<<<dim3(36, 72, NL), tb>>>(w2, w16 + OFF_W2,   FF, EDIM, FF,
                                      (size_t)FF * EDIM, (size_t)SZW2);
    convT_k<<<dim3(1407, 18, 1), tb>>>(wh, w16 + OFF_WH,  EDIM, VOC, KP, 0, 0);

    embed_ln_k<<<MM, 256>>>(index, tok, pos, ln1g, ln1b, x, y16);

    for (int l = 0; l < NL; l++) {
        const __half* pq  = w16 + OFF_QKV + (size_t)l * 3 * SZQ;
        const __half* po  = w16 + OFF_WO + (size_t)l * SZWO;
        const __half* p1  = w16 + OFF_W1 + (size_t)l * SZW1;
        const __half* p2  = w16 + OFF_W2 + (size_t)l * SZW2;
        const float* pbo = bo + (size_t)l * EDIM;
        const float* g2  = ln2g + (size_t)l * EDIM;
        const float* be2 = ln2b + (size_t)l * EDIM;
        const float* pb1 = b1 + (size_t)l * FF;
        const float* pb2 = b2 + (size_t)l * EDIM;
        const float* gn  = (l + 1 < NL) ? ln1g + (size_t)(l + 1) * EDIM : lnfg;
        const float* bn_ = (l + 1 < NL) ? ln1b + (size_t)(l + 1) * EDIM : lnfb;

        // QKV: N=3360, BN=96 (280 CTAs, 0.95 waves)
        hgemm_k<96><<<dim3(35, 8, 1), 256, DS96>>>(
            y16, pq, nullptr, qkv, nullptr, QKVN, KP, KP, QKVN, 0, 0);

        attn_k<<<dim3(BB * NH, 8), 128>>>(qkv, att16);

        // wo: split-K x4 (bias folded into z=0), then fused reduce+residual+LN2
        hgemm_k<128><<<dim3(9, 8, 4), 256, DS128>>>(
            att16, po, pbo, part, nullptr, EDIM, HH, HH, EDIM, 4, 280);
        reduce4ln_k<<<MM, 256>>>(part, x, g2, be2, y16);

        // w1: relu(y @ w1 + b1) -> fp16 h
        hgemm_k<128><<<dim3(36, 8, 1), 256, DS128>>>(
            y16, p1, pb1, nullptr, h16, FF, KP, KP, FF, 2, 0);

        // w2: split-K x4 (bias folded into z=0), then fused reduce+residual+LN
        hgemm_k<128><<<dim3(9, 8, 4), 256, DS128>>>(
            h16, p2, pb2, part, nullptr, EDIM, FF, FF, EDIM, 4, 1152);
        reduce4ln_k<<<MM, 256>>>(part, x, gn, bn_, y16);
    }

    // head: logits = lnf(x) @ wh + bh
    hgemm_k<128><<<dim3(352, 8, 1), 256, DS128>>>(
        y16, w16 + OFF_WH, bh, out, nullptr, VOC, KP, KP, VOC, 1, 0);
}

// round 15
// speedup vs baseline: 1.0376x; 1.0376x over previous
#include <cuda_runtime.h>
#include <cuda_fp16.h>
#include <cstdint>
#include <math.h>

// ---------------- problem constants ----------------
#define EDIM 1140
#define KP   1144            // EDIM padded to mult of 8 (fp16 16B chunks)
#define HH   1120
#define NH   32
#define HS   35
#define NL   36
#define VOC  45000
#define TT   128
#define BB   8
#define MM   1024
#define FF   4560
#define QKVN 3360
#define ATT_SCALE 0.16903085094570331f

// ---------------- converted-weight layout (fp16, transposed [N][K]) ----------------
#define SZQ  (1120*KP)
#define OFF_QKV ((size_t)0)
#define SZWO (1140*1120)
#define OFF_WO  ((size_t)NL*3*SZQ)
#define SZW1 (4560*KP)
#define OFF_W1  (OFF_WO + (size_t)NL*SZWO)
#define SZW2 (1140*4560)
#define OFF_W2  (OFF_W1 + (size_t)NL*SZW1)
#define OFF_WH  (OFF_W2 + (size_t)NL*SZW2)
#define WTOT    (OFF_WH + (size_t)VOC*KP)

// ---------------- scratch (device globals) ----------------
__device__ float  g_x[MM * EDIM];
__device__ float  g_qkv[MM * QKVN];
__device__ float  g_part[4 * MM * EDIM];
__device__ __half g_y16[MM * KP];
__device__ __half g_att16[MM * HH];
__device__ __half g_h16[MM * FF];
__device__ __half g_w16[WTOT];
__device__ int    g_is64;

// ---------------- helpers ----------------
__device__ __forceinline__ uint32_t smem_u32(const void* p) {
    uint32_t a;
    asm("{ .reg .u64 t; cvta.to.shared.u64 t, %1; cvt.u32.u64 %0, t; }" : "=r"(a) : "l"(p));
    return a;
}
__device__ __forceinline__ void cpa16(uint32_t s, const void* g) {
    asm volatile("cp.async.cg.shared.global [%0], [%1], 16;" :: "r"(s), "l"(g) : "memory");
}
__device__ __forceinline__ void zfill16(uint32_t s) {
    asm volatile("st.shared.v4.b32 [%0], {%1,%1,%1,%1};" :: "r"(s), "r"(0) : "memory");
}
__device__ __forceinline__ void mma_f16(float* d, const uint32_t* a, const uint32_t* b) {
    asm volatile(
        "mma.sync.aligned.m16n8k16.row.col.f32.f16.f16.f32 "
        "{%0,%1,%2,%3}, {%4,%5,%6,%7}, {%8,%9}, {%0,%1,%2,%3};"
        : "+f"(d[0]), "+f"(d[1]), "+f"(d[2]), "+f"(d[3])
        : "r"(a[0]), "r"(a[1]), "r"(a[2]), "r"(a[3]), "r"(b[0]), "r"(b[1]));
}
__device__ __forceinline__ void ldsm4(uint32_t* r, uint32_t a) {
    asm volatile("ldmatrix.sync.aligned.m8n8.x4.shared.b16 {%0,%1,%2,%3}, [%4];"
        : "=r"(r[0]), "=r"(r[1]), "=r"(r[2]), "=r"(r[3]) : "r"(a));
}
__device__ __forceinline__ void ldsm2(uint32_t* r, uint32_t a) {
    asm volatile("ldmatrix.sync.aligned.m8n8.x2.shared.b16 {%0,%1}, [%2];"
        : "=r"(r[0]), "=r"(r[1]) : "r"(a));
}

// ---------------- index dtype detection ----------------
__global__ void detect_k(const int* __restrict__ raw) {
    __shared__ int any;
    if (threadIdx.x == 0) any = 0;
    __syncthreads();
    int local = 0;
    for (int i = threadIdx.x; i < 512; i += blockDim.x)
        if (raw[2 * i + 1] != 0) local = 1;
    if (local) atomicOr(&any, 1);
    __syncthreads();
    if (threadIdx.x == 0) g_is64 = any ? 0 : 1;
}

// ---------------- weight convert: f32 [K][N] -> fp16 [N][KPad] (RN), zero K-pad ----------
__global__ void convT_k(const float* __restrict__ in, __half* __restrict__ out,
                        int K, int N, int KPad, size_t inLs, size_t outLs) {
    in  += (size_t)blockIdx.z * inLs;
    out += (size_t)blockIdx.z * outLs;
    __shared__ float t[64][33];
    int bn = blockIdx.x * 32, bk = blockIdx.y * 64;
    int x = threadIdx.x, y = threadIdx.y;
#pragma unroll
    for (int i = 0; i < 64; i += 8) {
        int k = bk + y + i, n = bn + x;
        t[y + i][x] = (k < K && n < N) ? in[(size_t)k * N + n] : 0.f;
    }
    __syncthreads();
#pragma unroll
    for (int i = 0; i < 32; i += 8) {
        int n = bn + y + i;
        int k = bk + 2 * x;
        if (n < N && k < KPad) {
            __half2 h = __halves2half2(__float2half_rn(t[2 * x][y + i]),
                                       __float2half_rn(t[2 * x + 1][y + i]));
            *(__half2*)(out + (size_t)n * KPad + k) = h;
        }
    }
}

// ---------------- block row-LN from smem values -> y16 (fp16, zero-padded to KP) ----------------
__device__ __forceinline__ void row_ln_emit(const float* v, float s, float s2,
                                            const float* g, const float* b,
                                            __half* yrow) {
    __shared__ float sh0[8], sh1[8];
    for (int o = 16; o > 0; o >>= 1) {
        s  += __shfl_down_sync(0xffffffffu, s, o);
        s2 += __shfl_down_sync(0xffffffffu, s2, o);
    }
    int w = threadIdx.x >> 5, lane = threadIdx.x & 31;
    if (lane == 0) { sh0[w] = s; sh1[w] = s2; }
    __syncthreads();
    if (threadIdx.x == 0) {
        float ts = 0.f, ts2 = 0.f;
        for (int i = 0; i < 8; i++) { ts += sh0[i]; ts2 += sh1[i]; }
        float mu = ts / (float)EDIM;
        float var = ts2 / (float)EDIM - mu * mu;
        sh0[0] = mu;
        sh1[0] = rsqrtf(var + 1e-5f);
    }
    __syncthreads();
    float mu = sh0[0], rstd = sh1[0];
    for (int c = threadIdx.x; c < KP; c += blockDim.x) {
        float o = (c < EDIM) ? (v[c] - mu) * rstd * g[c] + b[c] : 0.f;
        yrow[c] = __float2half_rn(o);
    }
}

// ---------------- embedding + LN1(layer0) ----------------
__global__ void embed_ln_k(const int* __restrict__ raw,
                           const float* __restrict__ tok,
                           const float* __restrict__ pos,
                           const float* __restrict__ g,
                           const float* __restrict__ b,
                           float* __restrict__ x, __half* __restrict__ y16) {
    __shared__ float v[EDIM];
    int r = blockIdx.x, t = r % TT;
    int idx = g_is64 ? raw[2 * r] : raw[r];
    const float* te = tok + (size_t)idx * EDIM;
    const float* pe = pos + (size_t)t * EDIM;
    float s = 0.f, s2 = 0.f;
    for (int c = threadIdx.x; c < EDIM; c += blockDim.x) {
        float val = te[c] + pe[c];
        v[c] = val;
        x[(size_t)r * EDIM + c] = val;
        s += val; s2 = fmaf(val, val, s2);
    }
    __syncthreads();
    row_ln_emit(v, s, s2, g, b, y16 + (size_t)r * KP);
}

// ---------------- split-K reduce + residual + bias -> x; then LN -> y16 (float4) -------------
__global__ void reduce4ln_k(const float* __restrict__ part,
                            const float* __restrict__ bias,
                            float* __restrict__ x,
                            const float* __restrict__ g,
                            const float* __restrict__ b,
                            __half* __restrict__ y16) {
    __shared__ float v[EDIM];
    int r = blockIdx.x;
    const float4* p0 = (const float4*)(part + (size_t)r * EDIM);
    const float4* p1 = (const float4*)(part + (size_t)MM * EDIM + (size_t)r * EDIM);
    const float4* p2 = (const float4*)(part + (size_t)2 * MM * EDIM + (size_t)r * EDIM);
    const float4* p3 = (const float4*)(part + (size_t)3 * MM * EDIM + (size_t)r * EDIM);
    const float4* bb = (const float4*)bias;
    float4* xr = (float4*)(x + (size_t)r * EDIM);
    float s = 0.f, s2 = 0.f;
    for (int c = threadIdx.x; c < EDIM / 4; c += blockDim.x) {
        float4 a0 = p0[c], a1 = p1[c], a2 = p2[c], a3 = p3[c];
        float4 bv = bb[c], xv = xr[c];
        float4 val;
        val.x = ((a0.x + a1.x) + (a2.x + a3.x)) + bv.x + xv.x;
        val.y = ((a0.y + a1.y) + (a2.y + a3.y)) + bv.y + xv.y;
        val.z = ((a0.z + a1.z) + (a2.z + a3.z)) + bv.z + xv.z;
        val.w = ((a0.w + a1.w) + (a2.w + a3.w)) + bv.w + xv.w;
        xr[c] = val;
        *(float4*)(v + 4 * c) = val;
        s += val.x + val.y + val.z + val.w;
        s2 = fmaf(val.x, val.x, s2);
        s2 = fmaf(val.y, val.y, s2);
        s2 = fmaf(val.z, val.z, s2);
        s2 = fmaf(val.w, val.w, s2);
    }
    __syncthreads();
    row_ln_emit(v, s, s2, g, b, y16 + (size_t)r * KP);
}

// ---------------- fp16 tensor-core GEMM (BKK=64, 3-stage), templated on BN ----------------
#define BKK 64
#define ASTH 72                         // smem pitch in halfs (144 B, ldsm conflict-free)
#define NSTG 3

template<int BN>
__device__ __forceinline__ void load_slab_h(const __half* __restrict__ A,
                                            const __half* __restrict__ B,
                                            int Nc, int lda, int kend,
                                            int bm, int bn, int k0,
                                            uint32_t sA, uint32_t sB, int tid) {
#pragma unroll
    for (int i = 0; i < 4; i++) {                  // A: 128 rows x 64 k
        int c = tid + i * 256;
        int row = c >> 3;
        int kc = (c & 7) * 8;
        int gk = k0 + kc;
        uint32_t off = sA + (uint32_t)(row * ASTH + kc) * 2;
        if (gk < kend) cpa16(off, A + (size_t)(bm + row) * lda + gk);
        else           zfill16(off);
    }
#pragma unroll
    for (int i = 0; i < BN / 32; i++) {            // B: BN n-rows x 64 k
        int c = tid + i * 256;
        int row = c >> 3;
        int kc = (c & 7) * 8;
        int gk = k0 + kc;
        uint32_t off = sB + (uint32_t)(row * ASTH + kc) * 2;
        if (gk < kend && (bn + row) < Nc) cpa16(off, B + (size_t)(bn + row) * lda + gk);
        else                              zfill16(off);
    }
}

template<int BN>
__global__ void __launch_bounds__(256, 2)
hgemm_k(const __half* __restrict__ A,
        const __half* __restrict__ B0, const __half* __restrict__ B1,
        const __half* __restrict__ B2,
        const float* __restrict__ bias,
        float* __restrict__ C, __half* __restrict__ C16,
        int Nc, int K, int lda, int ldc, int zoff, int mode, int kchunk) {
    constexpr int NT = BN / 32;                 // n-subtiles per warp
    constexpr int WNT = NT * 8;                 // warp n-tile
    constexpr int STG_H = (128 + BN) * ASTH;

    extern __shared__ __half smh[];

    int z = blockIdx.z;
    const __half* Bm;
    int coff, kb, ke;
    size_t rowoff;
    if (kchunk > 0) {
        Bm = B0; coff = 0;
        kb = z * kchunk;
        ke = min(K, kb + kchunk);
        rowoff = (size_t)z * MM;
    } else {
        Bm = (z == 0) ? B0 : ((z == 1) ? B1 : B2);
        coff = z * zoff;
        kb = 0; ke = K;
        rowoff = 0;
    }

    int tid = threadIdx.x;
    int bn = blockIdx.x * BN, bm = blockIdx.y * 128;
    int warp = tid >> 5, lane = tid & 31;
    int wm = warp >> 2, wn = warp & 3;          // 2 x 4 warp grid
    int g = lane >> 2, tig = lane & 3;

    int lrow = lane & 15;
    int koff8 = (lane & 16) ? 8 : 0;
    int l8 = lane & 7;
    int koff8b = (lane & 8) ? 8 : 0;

    uint32_t sbase = smem_u32(smh);

    float acc[4][NT][4];
#pragma unroll
    for (int mt = 0; mt < 4; mt++)
#pragma unroll
        for (int nt = 0; nt < NT; nt++)
#pragma unroll
            for (int j = 0; j < 4; j++) acc[mt][nt][j] = 0.f;

    const int NS = (ke - kb + BKK - 1) / BKK;

    // prologue: stages 0,1 in flight
#pragma unroll
    for (int s = 0; s < 2; s++) {
        if (s < NS)
            load_slab_h<BN>(A, Bm, Nc, lda, ke, bm, bn, kb + s * BKK,
                            sbase + (uint32_t)(s * STG_H) * 2,
                            sbase + (uint32_t)(s * STG_H + 128 * ASTH) * 2, tid);
        asm volatile("cp.async.commit_group;" ::: "memory");
    }
    asm volatile("cp.async.wait_group 1;" ::: "memory");   // stage 0 ready
    __syncthreads();

    int cst = 0, lst = 2;

    for (int ksl = 0; ksl < NS; ksl++) {
        uint32_t sA = sbase + (uint32_t)(cst * STG_H) * 2;
        uint32_t sB = sA + (uint32_t)(128 * ASTH) * 2;
        uint32_t aw = sA + (uint32_t)((wm * 64 + lrow) * ASTH + koff8) * 2;
        uint32_t bw = sB + (uint32_t)((wn * WNT + lrow) * ASTH + koff8) * 2;
        uint32_t bw2 = sB + (uint32_t)((wn * WNT + 16 + l8) * ASTH + koff8b) * 2;

        // compute this slab: 4 k-slices of 16
#pragma unroll
        for (int ks = 0; ks < 4; ks++) {
            uint32_t kb2 = (uint32_t)(ks * 16) * 2;
            uint32_t a[4][4];
#pragma unroll
            for (int mt = 0; mt < 4; mt++)
                ldsm4(a[mt], aw + (uint32_t)(mt * 16 * ASTH) * 2 + kb2);

            uint32_t bcol[NT][2];
            if (BN == 128) {
                uint32_t b0[4], b1[4];
                ldsm4(b0, bw + kb2);
                ldsm4(b1, bw + (uint32_t)(16 * ASTH) * 2 + kb2);
                bcol[0][0] = b0[0]; bcol[0][1] = b0[2];
                bcol[1][0] = b0[1]; bcol[1][1] = b0[3];
                bcol[2][0] = b1[0]; bcol[2][1] = b1[2];
                bcol[NT - 1][0] = b1[1]; bcol[NT - 1][1] = b1[3];
            } else {
                uint32_t b0[4], b1[2];
                ldsm4(b0, bw + kb2);
                ldsm2(b1, bw2 + kb2);
                bcol[0][0] = b0[0]; bcol[0][1] = b0[2];
                bcol[1][0] = b0[1]; bcol[1][1] = b0[3];
                bcol[NT - 1][0] = b1[0]; bcol[NT - 1][1] = b1[1];
            }
#pragma unroll
            for (int mt = 0; mt < 4; mt++)
#pragma unroll
                for (int nt = 0; nt < NT; nt++)
                    mma_f16(acc[mt][nt], a[mt], bcol[nt]);
        }

        // issue loads for slab ksl+2 (buffer consumed at ksl-1; barrier-separated)
        if (ksl + 2 < NS)
            load_slab_h<BN>(A, Bm, Nc, lda, ke, bm, bn, kb + (ksl + 2) * BKK,
                            sbase + (uint32_t)(lst * STG_H) * 2,
                            sbase + (uint32_t)(lst * STG_H + 128 * ASTH) * 2, tid);
        asm volatile("cp.async.commit_group;" ::: "memory");
        asm volatile("cp.async.wait_group 1;" ::: "memory");  // stage ksl+1 ready
        __syncthreads();

        if (++cst == NSTG) cst = 0;
        if (++lst == NSTG) lst = 0;
    }

    // epilogue
    bool fullN = (bn + BN) <= Nc;
#pragma unroll
    for (int mt = 0; mt < 4; mt++) {
        size_t r0 = rowoff + bm + wm * 64 + mt * 16 + g;
        size_t r1 = r0 + 8;
#pragma unroll
        for (int nt = 0; nt < NT; nt++) {
            int lcol = bn + wn * WNT + nt * 8 + 2 * tig;
            int col = coff + lcol;
            float v0 = acc[mt][nt][0], v1 = acc[mt][nt][1];
            float v2 = acc[mt][nt][2], v3 = acc[mt][nt][3];
            if (fullN) {
                if (mode == 1 || mode == 2) {
                    float2 bb = *(const float2*)(bias + lcol);
                    v0 += bb.x; v1 += bb.y; v2 += bb.x; v3 += bb.y;
                }
                if (mode == 2) {
                    __half2 h0 = __halves2half2(__float2half_rn(fmaxf(v0, 0.f)),
                                                __float2half_rn(fmaxf(v1, 0.f)));
                    __half2 h1 = __halves2half2(__float2half_rn(fmaxf(v2, 0.f)),
                                                __float2half_rn(fmaxf(v3, 0.f)));
                    *(__half2*)(C16 + r0 * ldc + col) = h0;
                    *(__half2*)(C16 + r1 * ldc + col) = h1;
                } else {
                    *(float2*)(C + r0 * ldc + col) = make_float2(v0, v1);
                    *(float2*)(C + r1 * ldc + col) = make_float2(v2, v3);
                }
            } else {
                float vv[4] = {v0, v1, v2, v3};
                size_t rr[4] = {r0, r0, r1, r1};
                int cc[4] = {lcol, lcol + 1, lcol, lcol + 1};
#pragma unroll
                for (int j = 0; j < 4; j++) {
                    if (cc[j] >= Nc) continue;
                    float v = vv[j];
                    if (mode == 1 || mode == 2) v += bias[cc[j]];
                    if (mode == 2)
                        C16[rr[j] * ldc + coff + cc[j]] = __float2half_rn(fmaxf(v, 0.f));
                    else
                        C[rr[j] * ldc + coff + cc[j]] = v;
                }
            }
        }
    }
}

#define DS96  (NSTG * (128 + 96)  * ASTH * 2)   // 96768 B
#define DS128 (NSTG * (128 + 128) * ASTH * 2)   // 110592 B

// ---------------- attention: 8-way split over s per query, shfl merge ----------------
// __expf: hardware MUFU.EX2 path (~1e-6 rel err) instead of precise-polynomial expf.
__global__ void __launch_bounds__(128)
attn_k(const float* __restrict__ qkv, __half* __restrict__ att) {
    __shared__ float ks[TT][HS + 1];
    __shared__ float vs[TT][HS + 1];

    int bh = blockIdx.x;
    int b = bh / NH, h = bh % NH;
    int qy = blockIdx.y;
    int tid = threadIdx.x;
    int t = qy * 16 + (tid >> 3);
    int sub = tid & 7;
    const size_t rbase = (size_t)b * TT * QKVN;
    const int hoff = h * HS;
    const int rows = qy * 16 + 16;      // causal trim

    for (int idx = tid; idx < rows * HS; idx += 128) {
        int s = idx / HS, d = idx % HS;
        ks[s][d] = qkv[rbase + (size_t)s * QKVN + HH + hoff + d];
        vs[s][d] = qkv[rbase + (size_t)s * QKVN + 2 * HH + hoff + d];
    }
    __syncthreads();

    float qreg[HS];
#pragma unroll
    for (int d = 0; d < HS; d++)
        qreg[d] = qkv[rbase + (size_t)t * QKVN + hoff + d];

    float m = -1e30f, l = 0.f;
    float out[HS];
#pragma unroll
    for (int d = 0; d < HS; d++) out[d] = 0.f;

    for (int s = sub; s <= t; s += 8) {
        float dot = 0.f;
#pragma unroll
        for (int d = 0; d < HS; d++)
            dot = fmaf(qreg[d], ks[s][d], dot);
        float sc = dot * ATT_SCALE;
        float mn = fmaxf(m, sc);
        float corr = __expf(m - mn);
        float p = __expf(sc - mn);
        l = l * corr + p;
#pragma unroll
        for (int d = 0; d < HS; d++)
            out[d] = out[d] * corr + p * vs[s][d];
        m = mn;
    }

    float M = m;
#pragma unroll
    for (int o = 1; o < 8; o <<= 1)
        M = fmaxf(M, __shfl_xor_sync(0xffffffffu, M, o));
    float e = __expf(m - M);
    float ls = l * e;
#pragma unroll
    for (int o = 1; o < 8; o <<= 1)
        ls += __shfl_xor_sync(0xffffffffu, ls, o);
    float inv = 1.f / ls;

    size_t obase = (size_t)(b * TT + t) * HH + hoff;
#pragma unroll
    for (int d = 0; d < HS; d++) {
        float ov = out[d] * e;
#pragma unroll
        for (int o2 = 1; o2 < 8; o2 <<= 1)
            ov += __shfl_xor_sync(0xffffffffu, ov, o2);
        if (sub == 0) att[obase + d] = __float2half_rn(ov * inv);
    }
}

// ---------------- launcher ----------------
extern "C" void kernel_launch(void* const* d_in, const int* in_sizes, int n_in,
                              void* d_out, int out_size) {
    (void)in_sizes; (void)n_in; (void)out_size;
    const int*   index = (const int*)  d_in[0];
    const float* tok   = (const float*)d_in[1];
    const float* pos   = (const float*)d_in[2];
    const float* wq    = (const float*)d_in[3];
    const float* wk    = (const float*)d_in[4];
    const float* wv    = (const float*)d_in[5];
    const float* wo    = (const float*)d_in[6];
    const float* bo    = (const float*)d_in[7];
    const float* ln1g  = (const float*)d_in[8];
    const float* ln1b  = (const float*)d_in[9];
    const float* ln2g  = (const float*)d_in[10];
    const float* ln2b  = (const float*)d_in[11];
    const float* w1    = (const float*)d_in[12];
    const float* b1    = (const float*)d_in[13];
    const float* w2    = (const float*)d_in[14];
    const float* b2    = (const float*)d_in[15];
    const float* lnfg  = (const float*)d_in[16];
    const float* lnfb  = (const float*)d_in[17];
    const float* wh    = (const float*)d_in[18];
    const float* bh    = (const float*)d_in[19];
    float* out = (float*)d_out;

    float *x, *qkv, *part;
    __half *y16, *att16, *h16, *w16;
    cudaGetSymbolAddress((void**)&x,     g_x);
    cudaGetSymbolAddress((void**)&qkv,   g_qkv);
    cudaGetSymbolAddress((void**)&part,  g_part);
    cudaGetSymbolAddress((void**)&y16,   g_y16);
    cudaGetSymbolAddress((void**)&att16, g_att16);
    cudaGetSymbolAddress((void**)&h16,   g_h16);
    cudaGetSymbolAddress((void**)&w16,   g_w16);

    cudaFuncSetAttribute(hgemm_k<128>, cudaFuncAttributeMaxDynamicSharedMemorySize, DS128);
    cudaFuncSetAttribute(hgemm_k<96>,  cudaFuncAttributeMaxDynamicSharedMemorySize, DS96);

    dim3 tb(32, 8);

    detect_k<<<1, 256>>>(index);

    // ---- convert all weights: f32 [K][N] -> fp16 [N][KPad], once per launch ----
    convT_k<<<dim3(35, 18, NL), tb>>>(wq, w16 + OFF_QKV,            EDIM, HH, KP,
                                      (size_t)EDIM * HH, (size_t)3 * SZQ);
    convT_k<<<dim3(35, 18, NL), tb>>>(wk, w16 + OFF_QKV + SZQ,      EDIM, HH, KP,
                                      (size_t)EDIM * HH, (size_t)3 * SZQ);
    convT_k<<<dim3(35, 18, NL), tb>>>(wv, w16 + OFF_QKV + 2 * SZQ,  EDIM, HH, KP,
                                      (size_t)EDIM * HH, (size_t)3 * SZQ);
    convT_k<<<dim3(36, 18, NL), tb>>>(wo, w16 + OFF_WO,             HH, EDIM, HH,
                                      (size_t)HH * EDIM, (size_t)SZWO);
    convT_k<<<dim3(143, 18, NL), tb>>>(w1, w16 + OFF_W1,            EDIM, FF, KP,
                                      (size_t)EDIM * FF, (size_t)SZW1);
    convT_k<<<dim3(36, 72, NL), tb>>>(w2, w16 + OFF_W2,             FF, EDIM, FF,
                                      (size_t)FF * EDIM, (size_t)SZW2);
    convT_k<<<dim3(1407, 18, 1), tb>>>(wh, w16 + OFF_WH,            EDIM, VOC, KP,
                                      0, 0);

    embed_ln_k<<<MM, 256>>>(index, tok, pos, ln1g, ln1b, x, y16);

    for (int l = 0; l < NL; l++) {
        const __half* pq  = w16 + OFF_QKV + (size_t)l * 3 * SZQ;
        const __half* po  = w16 + OFF_WO + (size_t)l * SZWO;
        const __half* p1  = w16 + OFF_W1 + (size_t)l * SZW1;
        const __half* p2  = w16 + OFF_W2 + (size_t)l * SZW2;
        const float* pbo = bo + (size_t)l * EDIM;
        const float* g2  = ln2g + (size_t)l * EDIM;
        const float* be2 = ln2b + (size_t)l * EDIM;
        const float* pb1 = b1 + (size_t)l * FF;
        const float* pb2 = b2 + (size_t)l * EDIM;
        const float* gn  = (l + 1 < NL) ? ln1g + (size_t)(l + 1) * EDIM : lnfg;
        const float* bn_ = (l + 1 < NL) ? ln1b + (size_t)(l + 1) * EDIM : lnfb;

        // QKV: single GEMM N=3360 with BN=96 tiles (280 CTAs, 95% wave fill)
        hgemm_k<96><<<dim3(35, 8, 1), 256, DS96>>>(
            y16, pq, nullptr, nullptr, nullptr, qkv, nullptr,
            QKVN, KP, KP, QKVN, 0, 0, 0);

        attn_k<<<dim3(BB * NH, 8), 128>>>(qkv, att16);

        // wo: split-K x4 partials, then fused reduce+bias+residual+LN2
        hgemm_k<128><<<dim3(9, 8, 4), 256, DS128>>>(
            att16, po, nullptr, nullptr, nullptr, part, nullptr,
            EDIM, HH, HH, EDIM, 0, 4, 280);
        reduce4ln_k<<<MM, 256>>>(part, pbo, x, g2, be2, y16);

        // w1: relu(y @ w1 + b1) -> fp16 h
        hgemm_k<128><<<dim3(36, 8, 1), 256, DS128>>>(
            y16, p1, nullptr, nullptr, pb1, nullptr, h16, FF, KP, KP, FF, 0, 2, 0);

        // w2: split-K x4 partials, then fused reduce+bias+residual+LN (next ln1 / lnf)
        hgemm_k<128><<<dim3(9, 8, 4), 256, DS128>>>(
            h16, p2, nullptr, nullptr, nullptr, part, nullptr,
            EDIM, FF, FF, EDIM, 0, 4, 1152);
        reduce4ln_k<<<MM, 256>>>(part, pb2, x, gn, bn_, y16);
    }

    // head: logits = lnf(x) @ wh + bh
    hgemm_k<128><<<dim3(352, 8, 1), 256, DS128>>>(
        y16, w16 + OFF_WH, nullptr, nullptr, bh, out, nullptr,
        VOC, KP, KP, VOC, 0, 1, 0);
}

// round 17
// speedup vs baseline: 1.0379x; 1.0003x over previous
#include <cuda_runtime.h>
#include <cuda_fp16.h>
#include <cstdint>
#include <math.h>

// ---------------- problem constants ----------------
#define EDIM 1140
#define KP   1144            // EDIM padded to mult of 8 (fp16 16B chunks)
#define HH   1120
#define NH   32
#define HS   35
#define NL   36
#define VOC  45000
#define TT   128
#define BB   8
#define MM   1024
#define FF   4560
#define QKVN 3360
#define ATT_SCALE 0.16903085094570331f

// ---------------- converted-weight layout (fp16, transposed [N][K]) ----------------
#define SZQ  (1120*KP)
#define OFF_QKV ((size_t)0)
#define SZWO (1140*1120)
#define OFF_WO  ((size_t)NL*3*SZQ)
#define SZW1 (4560*KP)
#define OFF_W1  (OFF_WO + (size_t)NL*SZWO)
#define SZW2 (1140*4560)
#define OFF_W2  (OFF_W1 + (size_t)NL*SZW1)
#define OFF_WH  (OFF_W2 + (size_t)NL*SZW2)
#define WTOT    (OFF_WH + (size_t)VOC*KP)

// ---------------- scratch (device globals) ----------------
__device__ float  g_x[MM * EDIM];
__device__ float  g_qkv[MM * QKVN];
__device__ float  g_part[4 * MM * EDIM];
__device__ __half g_y16[MM * KP];
__device__ __half g_att16[MM * HH];
__device__ __half g_h16[MM * FF];
__device__ __half g_w16[WTOT];
__device__ int    g_is64;

// ---------------- helpers ----------------
__device__ __forceinline__ uint32_t smem_u32(const void* p) {
    uint32_t a;
    asm("{ .reg .u64 t; cvta.to.shared.u64 t, %1; cvt.u32.u64 %0, t; }" : "=r"(a) : "l"(p));
    return a;
}
__device__ __forceinline__ void cpa16(uint32_t s, const void* g) {
    asm volatile("cp.async.cg.shared.global [%0], [%1], 16;" :: "r"(s), "l"(g) : "memory");
}
__device__ __forceinline__ void zfill16(uint32_t s) {
    asm volatile("st.shared.v4.b32 [%0], {%1,%1,%1,%1};" :: "r"(s), "r"(0) : "memory");
}
__device__ __forceinline__ void mma_f16(float* d, const uint32_t* a, const uint32_t* b) {
    asm volatile(
        "mma.sync.aligned.m16n8k16.row.col.f32.f16.f16.f32 "
        "{%0,%1,%2,%3}, {%4,%5,%6,%7}, {%8,%9}, {%0,%1,%2,%3};"
        : "+f"(d[0]), "+f"(d[1]), "+f"(d[2]), "+f"(d[3])
        : "r"(a[0]), "r"(a[1]), "r"(a[2]), "r"(a[3]), "r"(b[0]), "r"(b[1]));
}
__device__ __forceinline__ void ldsm4(uint32_t* r, uint32_t a) {
    asm volatile("ldmatrix.sync.aligned.m8n8.x4.shared.b16 {%0,%1,%2,%3}, [%4];"
        : "=r"(r[0]), "=r"(r[1]), "=r"(r[2]), "=r"(r[3]) : "r"(a));
}
__device__ __forceinline__ void ldsm2(uint32_t* r, uint32_t a) {
    asm volatile("ldmatrix.sync.aligned.m8n8.x2.shared.b16 {%0,%1}, [%2];"
        : "=r"(r[0]), "=r"(r[1]) : "r"(a));
}

// ---------------- index dtype detection ----------------
__global__ void detect_k(const int* __restrict__ raw) {
    __shared__ int any;
    if (threadIdx.x == 0) any = 0;
    __syncthreads();
    int local = 0;
    for (int i = threadIdx.x; i < 512; i += blockDim.x)
        if (raw[2 * i + 1] != 0) local = 1;
    if (local) atomicOr(&any, 1);
    __syncthreads();
    if (threadIdx.x == 0) g_is64 = any ? 0 : 1;
}

// ---------------- weight convert: f32 [K][N] -> fp16 [N][KPad] (RN), zero K-pad ----------
// v2.1: smem staged transposed [n][k] pitch 69 (conflict-free load phase), SCALAR smem
// reads in store phase (pitch-69 rows are not 16B-aligned -> no vector smem loads),
// 8-byte coalesced global stores.
__global__ void convT_k(const float* __restrict__ in, __half* __restrict__ out,
                        int K, int N, int KPad, size_t inLs, size_t outLs) {
    in  += (size_t)blockIdx.z * inLs;
    out += (size_t)blockIdx.z * outLs;
    __shared__ float t[32][69];            // [n][k] 32 n-rows x 64 k, pitch 69
    int bn = blockIdx.x * 32, bk = blockIdx.y * 64;
    int x = threadIdx.x, y = threadIdx.y;  // (32, 8)
    // load phase: coalesced global reads; smem write banks (5x + ...) % 32, conflict-free
#pragma unroll
    for (int i = 0; i < 8; i++) {
        int k = bk + y + 8 * i;
        int n = bn + x;
        float v = (k < K && n < N) ? in[(size_t)k * N + n] : 0.f;
        t[x][y + 8 * i] = v;
    }
    __syncthreads();
    // store phase: scalar smem reads (aligned), 8B global stores
#pragma unroll
    for (int j = 0; j < 2; j++) {
        int lin = (y * 32 + x) + j * 256;      // 0..511
        int n = lin >> 4;                      // 0..31
        int q = lin & 15;                      // 0..15
        int gn = bn + n;
        int k = bk + 4 * q;
        if (gn < N && k < KPad) {
            float v0 = t[n][4 * q + 0];
            float v1 = t[n][4 * q + 1];
            float v2 = t[n][4 * q + 2];
            float v3 = t[n][4 * q + 3];
            __half2 p0 = __halves2half2(__float2half_rn(v0), __float2half_rn(v1));
            __half2 p1 = __halves2half2(__float2half_rn(v2), __float2half_rn(v3));
            uint2 u;
            u.x = *(const uint32_t*)&p0;
            u.y = *(const uint32_t*)&p1;
            *(uint2*)(out + (size_t)gn * KPad + k) = u;
        }
    }
}

// ---------------- block row-LN from smem values -> y16 (fp16, zero-padded to KP) ----------------
__device__ __forceinline__ void row_ln_emit(const float* v, float s, float s2,
                                            const float* g, const float* b,
                                            __half* yrow) {
    __shared__ float sh0[8], sh1[8];
    for (int o = 16; o > 0; o >>= 1) {
        s  += __shfl_down_sync(0xffffffffu, s, o);
        s2 += __shfl_down_sync(0xffffffffu, s2, o);
    }
    int w = threadIdx.x >> 5, lane = threadIdx.x & 31;
    if (lane == 0) { sh0[w] = s; sh1[w] = s2; }
    __syncthreads();
    if (threadIdx.x == 0) {
        float ts = 0.f, ts2 = 0.f;
        for (int i = 0; i < 8; i++) { ts += sh0[i]; ts2 += sh1[i]; }
        float mu = ts / (float)EDIM;
        float var = ts2 / (float)EDIM - mu * mu;
        sh0[0] = mu;
        sh1[0] = rsqrtf(var + 1e-5f);
    }
    __syncthreads();
    float mu = sh0[0], rstd = sh1[0];
    for (int c = threadIdx.x; c < KP; c += blockDim.x) {
        float o = (c < EDIM) ? (v[c] - mu) * rstd * g[c] + b[c] : 0.f;
        yrow[c] = __float2half_rn(o);
    }
}

// ---------------- embedding + LN1(layer0) ----------------
__global__ void embed_ln_k(const int* __restrict__ raw,
                           const float* __restrict__ tok,
                           const float* __restrict__ pos,
                           const float* __restrict__ g,
                           const float* __restrict__ b,
                           float* __restrict__ x, __half* __restrict__ y16) {
    __shared__ float v[EDIM];
    int r = blockIdx.x, t = r % TT;
    int idx = g_is64 ? raw[2 * r] : raw[r];
    const float* te = tok + (size_t)idx * EDIM;
    const float* pe = pos + (size_t)t * EDIM;
    float s = 0.f, s2 = 0.f;
    for (int c = threadIdx.x; c < EDIM; c += blockDim.x) {
        float val = te[c] + pe[c];
        v[c] = val;
        x[(size_t)r * EDIM + c] = val;
        s += val; s2 = fmaf(val, val, s2);
    }
    __syncthreads();
    row_ln_emit(v, s, s2, g, b, y16 + (size_t)r * KP);
}

// ---------------- split-K reduce + residual + bias -> x; then LN -> y16 (float4) -------------
__global__ void reduce4ln_k(const float* __restrict__ part,
                            const float* __restrict__ bias,
                            float* __restrict__ x,
                            const float* __restrict__ g,
                            const float* __restrict__ b,
                            __half* __restrict__ y16) {
    __shared__ float v[EDIM];
    int r = blockIdx.x;
    const float4* p0 = (const float4*)(part + (size_t)r * EDIM);
    const float4* p1 = (const float4*)(part + (size_t)MM * EDIM + (size_t)r * EDIM);
    const float4* p2 = (const float4*)(part + (size_t)2 * MM * EDIM + (size_t)r * EDIM);
    const float4* p3 = (const float4*)(part + (size_t)3 * MM * EDIM + (size_t)r * EDIM);
    const float4* bb = (const float4*)bias;
    float4* xr = (float4*)(x + (size_t)r * EDIM);
    float s = 0.f, s2 = 0.f;
    for (int c = threadIdx.x; c < EDIM / 4; c += blockDim.x) {
        float4 a0 = p0[c], a1 = p1[c], a2 = p2[c], a3 = p3[c];
        float4 bv = bb[c], xv = xr[c];
        float4 val;
        val.x = ((a0.x + a1.x) + (a2.x + a3.x)) + bv.x + xv.x;
        val.y = ((a0.y + a1.y) + (a2.y + a3.y)) + bv.y + xv.y;
        val.z = ((a0.z + a1.z) + (a2.z + a3.z)) + bv.z + xv.z;
        val.w = ((a0.w + a1.w) + (a2.w + a3.w)) + bv.w + xv.w;
        xr[c] = val;
        *(float4*)(v + 4 * c) = val;
        s += val.x + val.y + val.z + val.w;
        s2 = fmaf(val.x, val.x, s2);
        s2 = fmaf(val.y, val.y, s2);
        s2 = fmaf(val.z, val.z, s2);
        s2 = fmaf(val.w, val.w, s2);
    }
    __syncthreads();
    row_ln_emit(v, s, s2, g, b, y16 + (size_t)r * KP);
}

// ---------------- fp16 tensor-core GEMM (BKK=64, 3-stage), templated on BN ----------------
#define BKK 64
#define ASTH 72                         // smem pitch in halfs (144 B, ldsm conflict-free)
#define NSTG 3

template<int BN>
__device__ __forceinline__ void load_slab_h(const __half* __restrict__ A,
                                            const __half* __restrict__ B,
                                            int Nc, int lda, int kend,
                                            int bm, int bn, int k0,
                                            uint32_t sA, uint32_t sB, int tid) {
#pragma unroll
    for (int i = 0; i < 4; i++) {                  // A: 128 rows x 64 k
        int c = tid + i * 256;
        int row = c >> 3;
        int kc = (c & 7) * 8;
        int gk = k0 + kc;
        uint32_t off = sA + (uint32_t)(row * ASTH + kc) * 2;
        if (gk < kend) cpa16(off, A + (size_t)(bm + row) * lda + gk);
        else           zfill16(off);
    }
#pragma unroll
    for (int i = 0; i < BN / 32; i++) {            // B: BN n-rows x 64 k
        int c = tid + i * 256;
        int row = c >> 3;
        int kc = (c & 7) * 8;
        int gk = k0 + kc;
        uint32_t off = sB + (uint32_t)(row * ASTH + kc) * 2;
        if (gk < kend && (bn + row) < Nc) cpa16(off, B + (size_t)(bn + row) * lda + gk);
        else                              zfill16(off);
    }
}

template<int BN>
__global__ void __launch_bounds__(256, 2)
hgemm_k(const __half* __restrict__ A,
        const __half* __restrict__ B0, const __half* __restrict__ B1,
        const __half* __restrict__ B2,
        const float* __restrict__ bias,
        float* __restrict__ C, __half* __restrict__ C16,
        int Nc, int K, int lda, int ldc, int zoff, int mode, int kchunk) {
    constexpr int NT = BN / 32;                 // n-subtiles per warp
    constexpr int WNT = NT * 8;                 // warp n-tile
    constexpr int STG_H = (128 + BN) * ASTH;

    extern __shared__ __half smh[];

    int z = blockIdx.z;
    const __half* Bm;
    int coff, kb, ke;
    size_t rowoff;
    if (kchunk > 0) {
        Bm = B0; coff = 0;
        kb = z * kchunk;
        ke = min(K, kb + kchunk);
        rowoff = (size_t)z * MM;
    } else {
        Bm = (z == 0) ? B0 : ((z == 1) ? B1 : B2);
        coff = z * zoff;
        kb = 0; ke = K;
        rowoff = 0;
    }

    int tid = threadIdx.x;
    int bn = blockIdx.x * BN, bm = blockIdx.y * 128;
    int warp = tid >> 5, lane = tid & 31;
    int wm = warp >> 2, wn = warp & 3;          // 2 x 4 warp grid
    int g = lane >> 2, tig = lane & 3;

    int lrow = lane & 15;
    int koff8 = (lane & 16) ? 8 : 0;
    int l8 = lane & 7;
    int koff8b = (lane & 8) ? 8 : 0;

    uint32_t sbase = smem_u32(smh);

    float acc[4][NT][4];
#pragma unroll
    for (int mt = 0; mt < 4; mt++)
#pragma unroll
        for (int nt = 0; nt < NT; nt++)
#pragma unroll
            for (int j = 0; j < 4; j++) acc[mt][nt][j] = 0.f;

    const int NS = (ke - kb + BKK - 1) / BKK;

    // prologue: stages 0,1 in flight
#pragma unroll
    for (int s = 0; s < 2; s++) {
        if (s < NS)
            load_slab_h<BN>(A, Bm, Nc, lda, ke, bm, bn, kb + s * BKK,
                            sbase + (uint32_t)(s * STG_H) * 2,
                            sbase + (uint32_t)(s * STG_H + 128 * ASTH) * 2, tid);
        asm volatile("cp.async.commit_group;" ::: "memory");
    }
    asm volatile("cp.async.wait_group 1;" ::: "memory");   // stage 0 ready
    __syncthreads();

    int cst = 0, lst = 2;

    for (int ksl = 0; ksl < NS; ksl++) {
        uint32_t sA = sbase + (uint32_t)(cst * STG_H) * 2;
        uint32_t sB = sA + (uint32_t)(128 * ASTH) * 2;
        uint32_t aw = sA + (uint32_t)((wm * 64 + lrow) * ASTH + koff8) * 2;
        uint32_t bw = sB + (uint32_t)((wn * WNT + lrow) * ASTH + koff8) * 2;
        uint32_t bw2 = sB + (uint32_t)((wn * WNT + 16 + l8) * ASTH + koff8b) * 2;

        // compute this slab: 4 k-slices of 16
#pragma unroll
        for (int ks = 0; ks < 4; ks++) {
            uint32_t kb2 = (uint32_t)(ks * 16) * 2;
            uint32_t a[4][4];
#pragma unroll
            for (int mt = 0; mt < 4; mt++)
                ldsm4(a[mt], aw + (uint32_t)(mt * 16 * ASTH) * 2 + kb2);

            uint32_t bcol[NT][2];
            if (BN == 128) {
                uint32_t b0[4], b1[4];
                ldsm4(b0, bw + kb2);
                ldsm4(b1, bw + (uint32_t)(16 * ASTH) * 2 + kb2);
                bcol[0][0] = b0[0]; bcol[0][1] = b0[2];
                bcol[1][0] = b0[1]; bcol[1][1] = b0[3];
                bcol[2][0] = b1[0]; bcol[2][1] = b1[2];
                bcol[NT - 1][0] = b1[1]; bcol[NT - 1][1] = b1[3];
            } else {
                uint32_t b0[4], b1[2];
                ldsm4(b0, bw + kb2);
                ldsm2(b1, bw2 + kb2);
                bcol[0][0] = b0[0]; bcol[0][1] = b0[2];
                bcol[1][0] = b0[1]; bcol[1][1] = b0[3];
                bcol[NT - 1][0] = b1[0]; bcol[NT - 1][1] = b1[1];
            }
#pragma unroll
            for (int mt = 0; mt < 4; mt++)
#pragma unroll
                for (int nt = 0; nt < NT; nt++)
                    mma_f16(acc[mt][nt], a[mt], bcol[nt]);
        }

        // issue loads for slab ksl+2 (buffer consumed at ksl-1; barrier-separated)
        if (ksl + 2 < NS)
            load_slab_h<BN>(A, Bm, Nc, lda, ke, bm, bn, kb + (ksl + 2) * BKK,
                            sbase + (uint32_t)(lst * STG_H) * 2,
                            sbase + (uint32_t)(lst * STG_H + 128 * ASTH) * 2, tid);
        asm volatile("cp.async.commit_group;" ::: "memory");
        asm volatile("cp.async.wait_group 1;" ::: "memory");  // stage ksl+1 ready
        __syncthreads();

        if (++cst == NSTG) cst = 0;
        if (++lst == NSTG) lst = 0;
    }

    // epilogue
    bool fullN = (bn + BN) <= Nc;
#pragma unroll
    for (int mt = 0; mt < 4; mt++) {
        size_t r0 = rowoff + bm + wm * 64 + mt * 16 + g;
        size_t r1 = r0 + 8;
#pragma unroll
        for (int nt = 0; nt < NT; nt++) {
            int lcol = bn + wn * WNT + nt * 8 + 2 * tig;
            int col = coff + lcol;
            float v0 = acc[mt][nt][0], v1 = acc[mt][nt][1];
            float v2 = acc[mt][nt][2], v3 = acc[mt][nt][3];
            if (fullN) {
                if (mode == 1 || mode == 2) {
                    float2 bb = *(const float2*)(bias + lcol);
                    v0 += bb.x; v1 += bb.y; v2 += bb.x; v3 += bb.y;
                }
                if (mode == 2) {
                    __half2 h0 = __halves2half2(__float2half_rn(fmaxf(v0, 0.f)),
                                                __float2half_rn(fmaxf(v1, 0.f)));
                    __half2 h1 = __halves2half2(__float2half_rn(fmaxf(v2, 0.f)),
                                                __float2half_rn(fmaxf(v3, 0.f)));
                    *(__half2*)(C16 + r0 * ldc + col) = h0;
                    *(__half2*)(C16 + r1 * ldc + col) = h1;
                } else {
                    *(float2*)(C + r0 * ldc + col) = make_float2(v0, v1);
                    *(float2*)(C + r1 * ldc + col) = make_float2(v2, v3);
                }
            } else {
                float vv[4] = {v0, v1, v2, v3};
                size_t rr[4] = {r0, r0, r1, r1};
                int cc[4] = {lcol, lcol + 1, lcol, lcol + 1};
#pragma unroll
                for (int j = 0; j < 4; j++) {
                    if (cc[j] >= Nc) continue;
                    float v = vv[j];
                    if (mode == 1 || mode == 2) v += bias[cc[j]];
                    if (mode == 2)
                        C16[rr[j] * ldc + coff + cc[j]] = __float2half_rn(fmaxf(v, 0.f));
                    else
                        C[rr[j] * ldc + coff + cc[j]] = v;
                }
            }
        }
    }
}

#define DS96  (NSTG * (128 + 96)  * ASTH * 2)   // 96768 B
#define DS128 (NSTG * (128 + 128) * ASTH * 2)   // 110592 B

// ---------------- attention: 8-way split over s per query, shfl merge ----------------
__global__ void __launch_bounds__(128)
attn_k(const float* __restrict__ qkv, __half* __restrict__ att) {
    __shared__ float ks[TT][HS + 1];
    __shared__ float vs[TT][HS + 1];

    int bh = blockIdx.x;
    int b = bh / NH, h = bh % NH;
    int qy = blockIdx.y;
    int tid = threadIdx.x;
    int t = qy * 16 + (tid >> 3);
    int sub = tid & 7;
    const size_t rbase = (size_t)b * TT * QKVN;
    const int hoff = h * HS;
    const int rows = qy * 16 + 16;      // causal trim

    for (int idx = tid; idx < rows * HS; idx += 128) {
        int s = idx / HS, d = idx % HS;
        ks[s][d] = qkv[rbase + (size_t)s * QKVN + HH + hoff + d];
        vs[s][d] = qkv[rbase + (size_t)s * QKVN + 2 * HH + hoff + d];
    }
    __syncthreads();

    float qreg[HS];
#pragma unroll
    for (int d = 0; d < HS; d++)
        qreg[d] = qkv[rbase + (size_t)t * QKVN + hoff + d];

    float m = -1e30f, l = 0.f;
    float out[HS];
#pragma unroll
    for (int d = 0; d < HS; d++) out[d] = 0.f;

    for (int s = sub; s <= t; s += 8) {
        float dot = 0.f;
#pragma unroll
        for (int d = 0; d < HS; d++)
            dot = fmaf(qreg[d], ks[s][d], dot);
        float sc = dot * ATT_SCALE;
        float mn = fmaxf(m, sc);
        float corr = __expf(m - mn);
        float p = __expf(sc - mn);
        l = l * corr + p;
#pragma unroll
        for (int d = 0; d < HS; d++)
            out[d] = out[d] * corr + p * vs[s][d];
        m = mn;
    }

    float M = m;
#pragma unroll
    for (int o = 1; o < 8; o <<= 1)
        M = fmaxf(M, __shfl_xor_sync(0xffffffffu, M, o));
    float e = __expf(m - M);
    float ls = l * e;
#pragma unroll
    for (int o = 1; o < 8; o <<= 1)
        ls += __shfl_xor_sync(0xffffffffu, ls, o);
    float inv = 1.f / ls;

    size_t obase = (size_t)(b * TT + t) * HH + hoff;
#pragma unroll
    for (int d = 0; d < HS; d++) {
        float ov = out[d] * e;
#pragma unroll
        for (int o2 = 1; o2 < 8; o2 <<= 1)
            ov += __shfl_xor_sync(0xffffffffu, ov, o2);
        if (sub == 0) att[obase + d] = __float2half_rn(ov * inv);
    }
}

// ---------------- launcher ----------------
extern "C" void kernel_launch(void* const* d_in, const int* in_sizes, int n_in,
                              void* d_out, int out_size) {
    (void)in_sizes; (void)n_in; (void)out_size;
    const int*   index = (const int*)  d_in[0];
    const float* tok   = (const float*)d_in[1];
    const float* pos   = (const float*)d_in[2];
    const float* wq    = (const float*)d_in[3];
    const float* wk    = (const float*)d_in[4];
    const float* wv    = (const float*)d_in[5];
    const float* wo    = (const float*)d_in[6];
    const float* bo    = (const float*)d_in[7];
    const float* ln1g  = (const float*)d_in[8];
    const float* ln1b  = (const float*)d_in[9];
    const float* ln2g  = (const float*)d_in[10];
    const float* ln2b  = (const float*)d_in[11];
    const float* w1    = (const float*)d_in[12];
    const float* b1    = (const float*)d_in[13];
    const float* w2    = (const float*)d_in[14];
    const float* b2    = (const float*)d_in[15];
    const float* lnfg  = (const float*)d_in[16];
    const float* lnfb  = (const float*)d_in[17];
    const float* wh    = (const float*)d_in[18];
    const float* bh    = (const float*)d_in[19];
    float* out = (float*)d_out;

    float *x, *qkv, *part;
    __half *y16, *att16, *h16, *w16;
    cudaGetSymbolAddress((void**)&x,     g_x);
    cudaGetSymbolAddress((void**)&qkv,   g_qkv);
    cudaGetSymbolAddress((void**)&part,  g_part);
    cudaGetSymbolAddress((void**)&y16,   g_y16);
    cudaGetSymbolAddress((void**)&att16, g_att16);
    cudaGetSymbolAddress((void**)&h16,   g_h16);
    cudaGetSymbolAddress((void**)&w16,   g_w16);

    cudaFuncSetAttribute(hgemm_k<128>, cudaFuncAttributeMaxDynamicSharedMemorySize, DS128);
    cudaFuncSetAttribute(hgemm_k<96>,  cudaFuncAttributeMaxDynamicSharedMemorySize, DS96);

    dim3 tb(32, 8);

    detect_k<<<1, 256>>>(index);

    // ---- convert all weights: f32 [K][N] -> fp16 [N][KPad], once per launch ----
    convT_k<<<dim3(35, 18, NL), tb>>>(wq, w16 + OFF_QKV,            EDIM, HH, KP,
                                      (size_t)EDIM * HH, (size_t)3 * SZQ);
    convT_k<<<dim3(35, 18, NL), tb>>>(wk, w16 + OFF_QKV + SZQ,      EDIM, HH, KP,
                                      (size_t)EDIM * HH, (size_t)3 * SZQ);
    convT_k<<<dim3(35, 18, NL), tb>>>(wv, w16 + OFF_QKV + 2 * SZQ,  EDIM, HH, KP,
                                      (size_t)EDIM * HH, (size_t)3 * SZQ);
    convT_k<<<dim3(36, 18, NL), tb>>>(wo, w16 + OFF_WO,             HH, EDIM, HH,
                                      (size_t)HH * EDIM, (size_t)SZWO);
    convT_k<<<dim3(143, 18, NL), tb>>>(w1, w16 + OFF_W1,            EDIM, FF, KP,
                                      (size_t)EDIM * FF, (size_t)SZW1);
    convT_k<<<dim3(36, 72, NL), tb>>>(w2, w16 + OFF_W2,             FF, EDIM, FF,
                                      (size_t)FF * EDIM, (size_t)SZW2);
    convT_k<<<dim3(1407, 18, 1), tb>>>(wh, w16 + OFF_WH,            EDIM, VOC, KP,
                                      0, 0);

    embed_ln_k<<<MM, 256>>>(index, tok, pos, ln1g, ln1b, x, y16);

    for (int l = 0; l < NL; l++) {
        const __half* pq  = w16 + OFF_QKV + (size_t)l * 3 * SZQ;
        const __half* po  = w16 + OFF_WO + (size_t)l * SZWO;
        const __half* p1  = w16 + OFF_W1 + (size_t)l * SZW1;
        const __half* p2  = w16 + OFF_W2 + (size_t)l * SZW2;
        const float* pbo = bo + (size_t)l * EDIM;
        const float* g2  = ln2g + (size_t)l * EDIM;
        const float* be2 = ln2b + (size_t)l * EDIM;
        const float* pb1 = b1 + (size_t)l * FF;
        const float* pb2 = b2 + (size_t)l * EDIM;
        const float* gn  = (l + 1 < NL) ? ln1g + (size_t)(l + 1) * EDIM : lnfg;
        const float* bn_ = (l + 1 < NL) ? ln1b + (size_t)(l + 1) * EDIM : lnfb;

        // QKV: single GEMM N=3360 with BN=96 tiles (280 CTAs, 95% wave fill)
        hgemm_k<96><<<dim3(35, 8, 1), 256, DS96>>>(
            y16, pq, nullptr, nullptr, nullptr, qkv, nullptr,
            QKVN, KP, KP, QKVN, 0, 0, 0);

        attn_k<<<dim3(BB * NH, 8), 128>>>(qkv, att16);

        // wo: split-K x4 partials, then fused reduce+bias+residual+LN2
        hgemm_k<128><<<dim3(9, 8, 4), 256, DS128>>>(
            att16, po, nullptr, nullptr, nullptr, part, nullptr,
            EDIM, HH, HH, EDIM, 0, 4, 280);
        reduce4ln_k<<<MM, 256>>>(part, pbo, x, g2, be2, y16);

        // w1: relu(y @ w1 + b1) -> fp16 h
        hgemm_k<128><<<dim3(36, 8, 1), 256, DS128>>>(
            y16, p1, nullptr, nullptr, pb1, nullptr, h16, FF, KP, KP, FF, 0, 2, 0);

        // w2: split-K x4 partials, then fused reduce+bias+residual+LN (next ln1 / lnf)
        hgemm_k<128><<<dim3(9, 8, 4), 256, DS128>>>(
            h16, p2, nullptr, nullptr, nullptr, part, nullptr,
            EDIM, FF, FF, EDIM, 0, 4, 1152);
        reduce4ln_k<<<MM, 256>>>(part, pb2, x, gn, bn_, y16);
    }

    // head: logits = lnf(x) @ wh + bh
    hgemm_k<128><<<dim3(352, 8, 1), 256, DS128>>>(
        y16, w16 + OFF_WH, nullptr, nullptr, bh, out, nullptr,
        VOC, KP, KP, VOC, 0, 1, 0);
}